// round 16
// baseline (speedup 1.0000x reference)
#include <cuda_runtime.h>
#include <cuda_fp16.h>
#include <cstdint>

#define NN   50000
#define EMAX 800000
#define DH   256
#define SCAN_B 1024
#define NBLK ((NN + SCAN_B - 1) / SCAN_B)   // 49
#define PUB_FLAG 0x40000000

// ---------------- scratch (device globals; allocation-free) ----------------
__device__ __align__(16) int    g_deg[NN];        // zero at load; self-restored each launch
__device__ __align__(16) int    g_off[NN + 1];
__device__ __align__(16) int    g_cur[NN];
__device__ __align__(16) int    g_col[EMAX];
__device__ volatile int         g_pub[NBLK];      // packed aggregate | PUB_FLAG
__device__ __align__(16) __half g_xh  [(size_t)NN * 128];
__device__ __align__(16) __half g_w1lh[256 * 128];
__device__ __align__(16) __half g_w1rh[256 * 128];
__device__ __align__(16) __half g_w2lh[256 * 256];
__device__ __align__(16) __half g_w2rh[256 * 256];
__device__ __align__(16) __half g_m1h [(size_t)NN * 128];
__device__ __align__(16) __half g_h1h [(size_t)NN * 256];
__device__ __align__(16) __half g_m2h [(size_t)NN * 256];

// ---------------- helpers ----------------
__device__ __forceinline__ uint32_t smem_u32(const void* p) {
    uint32_t a;
    asm("{ .reg .u64 t; cvta.to.shared.u64 t, %1; cvt.u32.u64 %0, t; }" : "=r"(a) : "l"(p));
    return a;
}

__device__ __forceinline__ void cp16(uint32_t dst, const void* src, bool v) {
    int sz = v ? 16 : 0;
    asm volatile("cp.async.cg.shared.global [%0], [%1], 16, %2;\n"
                 :: "r"(dst), "l"(src), "r"(sz) : "memory");
}

__device__ __forceinline__ void mma_f16(float c[4], const uint32_t a[4], const uint32_t b[2]) {
    asm volatile(
        "mma.sync.aligned.m16n8k16.row.col.f32.f16.f16.f32 "
        "{%0,%1,%2,%3}, {%4,%5,%6,%7}, {%8,%9}, {%0,%1,%2,%3};\n"
        : "+f"(c[0]), "+f"(c[1]), "+f"(c[2]), "+f"(c[3])
        : "r"(a[0]), "r"(a[1]), "r"(a[2]), "r"(a[3]), "r"(b[0]), "r"(b[1]));
}

__device__ __forceinline__ void ldsm_x4(uint32_t r[4], uint32_t addr) {
    asm volatile("ldmatrix.sync.aligned.m8n8.x4.shared.b16 {%0,%1,%2,%3}, [%4];"
                 : "=r"(r[0]), "=r"(r[1]), "=r"(r[2]), "=r"(r[3]) : "r"(addr));
}

__device__ __forceinline__ void ldsm_x2(uint32_t& r0, uint32_t& r1, uint32_t addr) {
    asm volatile("ldmatrix.sync.aligned.m8n8.x2.shared.b16 {%0,%1}, [%2];"
                 : "=r"(r0), "=r"(r1) : "r"(addr));
}

__device__ __forceinline__ int warp_iscan(int x, int lane) {
#pragma unroll
    for (int o = 1; o < 32; o <<= 1) {
        int y = __shfl_up_sync(0xffffffffu, x, o);
        if (lane >= o) x += y;
    }
    return x;
}

// ---------------- fused prep: x->fp16, weights->fp16, degree count, flag reset ----
__global__ void k_prep(const float* __restrict__ x,
                       const float* __restrict__ W1l, const float* __restrict__ W1r,
                       const float* __restrict__ W2l, const float* __restrict__ W2r,
                       const int* __restrict__ dst, int E) {
    int i = blockIdx.x * blockDim.x + threadIdx.x;
    if (i < NBLK) g_pub[i] = 0;               // reset scan publication slots
    if (i < NN * 128 / 4) {
        float4 v = ((const float4*)x)[i];
        __half2 h0 = __floats2half2_rn(v.x, v.y);
        __half2 h1 = __floats2half2_rn(v.z, v.w);
        uint2 o;
        o.x = *(uint32_t*)&h0;
        o.y = *(uint32_t*)&h1;
        ((uint2*)g_xh)[i] = o;
    }
    if (i < 256 * 128) {
        g_w1lh[i] = __float2half_rn(W1l[i]);
        g_w1rh[i] = __float2half_rn(W1r[i]);
    }
    if (i < 256 * 256) {
        g_w2lh[i] = __float2half_rn(W2l[i]);
        g_w2rh[i] = __float2half_rn(W2r[i]);
    }
    if (i < E) atomicAdd(&g_deg[dst[i]], 1);  // g_deg pre-zeroed (load init / k_scan)
}

// ---------------- single-pass scan with decoupled lookback ----------------
__global__ void k_scan(int E, float* __restrict__ out) {
    __shared__ int wsum[32];
    __shared__ int s_prev;
    int t = threadIdx.x, lane = t & 31, w = t >> 5;
    int bid = blockIdx.x;
    int i = bid * SCAN_B + t;

    if (i < NN) out[i] = 0.f;                 // head accumulates into out later
    int v = 0;
    if (i < NN) {
        v = g_deg[i];
        g_deg[i] = 0;                         // self-restore for next launch
    }
    int x = warp_iscan(v, lane);
    if (lane == 31) wsum[w] = x;
    __syncthreads();
    if (w == 0) {
        int y = wsum[lane];
        int z = warp_iscan(y, lane);
        wsum[lane] = z - y;
    }
    __syncthreads();
    int incl = x + wsum[w];

    if (t == SCAN_B - 1) g_pub[bid] = incl | PUB_FLAG;

    if (w == 0) {
        int sum = 0;
        for (int b = bid - 1 - lane; b >= 0; b -= 32) {
            int p;
            do { p = g_pub[b]; } while (!(p & PUB_FLAG));
            sum += p & ~PUB_FLAG;
        }
#pragma unroll
        for (int o = 16; o; o >>= 1) sum += __shfl_xor_sync(0xffffffffu, sum, o);
        if (lane == 0) s_prev = sum;
    }
    __syncthreads();

    if (i < NN) {
        int e = incl - v + s_prev;
        g_off[i] = e;
        g_cur[i] = e;
    }
    if (i == 0) g_off[NN] = E;
}

__global__ void k_fill(const int* __restrict__ src, const int* __restrict__ dst, int E) {
    int e = blockIdx.x * blockDim.x + threadIdx.x;
    if (e < E) {
        int p = atomicAdd(&g_cur[dst[e]], 1);
        g_col[p] = src[e];
    }
}

// ---------------- aggregation: one warp per dst; depth-2 half tree, offset shfl ----
template <int D, int SEL>
__global__ void k_agg() {
    const __half* X   = (SEL == 0) ? g_xh  : g_h1h;
    __half*       OUT = (SEL == 0) ? g_m1h : g_m2h;

    int gw   = (blockIdx.x * blockDim.x + threadIdx.x) >> 5;
    int lane = threadIdx.x & 31;
    if (gw >= NN) return;

    constexpr int V2    = D / 128;             // uint2 (4 halves) per lane
    constexpr int BATCH = 8;                   // neighbors per inner step
    float acc[V2][4];
#pragma unroll
    for (int v = 0; v < V2; v++)
#pragma unroll
        for (int q = 0; q < 4; q++) acc[v][q] = 0.f;

    const char* Xb = (const char*)X;
    int s0 = g_off[gw], s1 = g_off[gw + 1];
    for (int i = s0; i < s1; i += 32) {
        int cnt = min(32, s1 - i);
        int my_off = 0;
        if (lane < cnt) my_off = g_col[i + lane] * (D * 2);   // byte offset (fits u32)
        int j = 0;
        for (; j + BATCH <= cnt; j += BATCH) {
            const uint2* p[BATCH];
#pragma unroll
            for (int b = 0; b < BATCH; b++) {
                int off = __shfl_sync(0xffffffffu, my_off, j + b);
                p[b] = (const uint2*)(Xb + off);
            }
            uint2 u[BATCH][V2];
#pragma unroll
            for (int b = 0; b < BATCH; b++)
#pragma unroll
                for (int v = 0; v < V2; v++) u[b][v] = p[b][v * 32 + lane];
            // depth-2 half2 tree (sum 4 neighbors in half), then fp32 accum
#pragma unroll
            for (int b = 0; b < BATCH; b += 4)
#pragma unroll
                for (int v = 0; v < V2; v++) {
                    __half2 px = __hadd2(
                        __hadd2(*(__half2*)&u[b + 0][v].x, *(__half2*)&u[b + 1][v].x),
                        __hadd2(*(__half2*)&u[b + 2][v].x, *(__half2*)&u[b + 3][v].x));
                    __half2 py = __hadd2(
                        __hadd2(*(__half2*)&u[b + 0][v].y, *(__half2*)&u[b + 1][v].y),
                        __hadd2(*(__half2*)&u[b + 2][v].y, *(__half2*)&u[b + 3][v].y));
                    float2 f0 = __half22float2(px);
                    float2 f1 = __half22float2(py);
                    acc[v][0] += f0.x; acc[v][1] += f0.y;
                    acc[v][2] += f1.x; acc[v][3] += f1.y;
                }
        }
        for (; j < cnt; j++) {                 // tail: exact fp32 path
            int off = __shfl_sync(0xffffffffu, my_off, j);
            const uint2* p = (const uint2*)(Xb + off);
#pragma unroll
            for (int v = 0; v < V2; v++) {
                uint2 u = p[v * 32 + lane];
                float2 f0 = __half22float2(*(__half2*)&u.x);
                float2 f1 = __half22float2(*(__half2*)&u.y);
                acc[v][0] += f0.x; acc[v][1] += f0.y;
                acc[v][2] += f1.x; acc[v][3] += f1.y;
            }
        }
    }
    int deg = s1 - s0;
    float inv = 1.0f / (float)max(deg, 1);
    uint2* orow = (uint2*)(OUT + (size_t)gw * D);
#pragma unroll
    for (int v = 0; v < V2; v++) {
        __half2 h0 = __floats2half2_rn(acc[v][0] * inv, acc[v][1] * inv);
        __half2 h1 = __floats2half2_rn(acc[v][2] * inv, acc[v][3] * inv);
        uint2 o;
        o.x = *(uint32_t*)&h0;
        o.y = *(uint32_t*)&h1;
        orow[v * 32 + lane] = o;
    }
}

// ---------------- fp16 mma.sync fused two-input GEMM + bias + ReLU ---------------
// SEL==0: C=h1 (fp16 store). SEL==1: head fused — out[n] += relu(row)·head_w (+hb).
#define PADH 40                              // halves per smem row (80 B)
#define TILE_BYTES (128 * PADH * 2)          // 10240
#define STAGE_BYTES (2 * TILE_BYTES)         // 20480 (A + W)
#define STAGE_HALVES (STAGE_BYTES / 2)

template <int K, int SEL>
__device__ __forceinline__ void load_chunk(int c, int m0, int n0, uint32_t sb, int tid) {
    constexpr int NCH = (2 * K) / 32;
    const __half* A1 = (SEL == 0) ? g_m1h  : g_m2h;
    const __half* A2 = (SEL == 0) ? g_xh   : g_h1h;
    const __half* W1 = (SEL == 0) ? g_w1lh : g_w2lh;
    const __half* W2 = (SEL == 0) ? g_w1rh : g_w2rh;

    int st = c & 1;
    int ss = (c >= NCH / 2);
    int k0 = (c - ss * (NCH / 2)) * 32;
    const __half* A = ss ? A2 : A1;
    const __half* W = ss ? W2 : W1;

    int row = tid >> 1;          // 0..127
    int q   = (tid & 1) * 2;     // 16B-chunk 0 or 2

    uint32_t base = sb + (uint32_t)st * STAGE_BYTES;
    uint32_t adst = base + row * (PADH * 2) + q * 16;
    uint32_t wdst = adst + TILE_BYTES;

    int  arow = m0 + row;
    bool v    = (arow < NN);
    int  ar   = v ? arow : 0;
    const __half* asrc = A + (size_t)ar * K + k0 + q * 8;
    const __half* wsrc = W + (size_t)(n0 + row) * K + k0 + q * 8;
    cp16(adst,      asrc,     v);
    cp16(adst + 16, asrc + 8, v);
    cp16(wdst,      wsrc,     true);
    cp16(wdst + 16, wsrc + 8, true);
    asm volatile("cp.async.commit_group;" ::: "memory");
}

template <int K, int SEL>
__global__ void __launch_bounds__(256, 2) k_gemm_h(const float* __restrict__ bias,
                                                   const float* __restrict__ HW,
                                                   const float* __restrict__ HB,
                                                   float* __restrict__ OUTP) {
    constexpr bool HEAD = (SEL == 1);
    constexpr int  NCH  = (2 * K) / 32;

    __shared__ __align__(16) __half smem[2 * STAGE_HALVES];
    __shared__ float sred[128][4];
    uint32_t sb = smem_u32(smem);

    const int tid  = threadIdx.x;
    const int warp = tid >> 5;
    const int lane = tid & 31;
    const int g    = lane >> 2;
    const int t    = lane & 3;
    const int m0   = blockIdx.x * 128;
    const int n0   = blockIdx.y * 128;
    const int wm   = warp >> 2;   // 0..1
    const int wn   = warp & 3;    // 0..3

    const int lr  = lane & 15;
    const int kc8 = (lane >> 4) * 8;
    const int bl  = lane & 7;
    const int bk8 = ((lane >> 3) & 1) * 8;

    float acc[4][4][4];
#pragma unroll
    for (int i = 0; i < 4; i++)
#pragma unroll
        for (int j = 0; j < 4; j++)
#pragma unroll
            for (int c = 0; c < 4; c++) acc[i][j][c] = 0.f;

    load_chunk<K, SEL>(0, m0, n0, sb, tid);

    for (int c = 0; c < NCH; c++) {
        if (c + 1 < NCH) {
            load_chunk<K, SEL>(c + 1, m0, n0, sb, tid);
            asm volatile("cp.async.wait_group 1;" ::: "memory");
        } else {
            asm volatile("cp.async.wait_group 0;" ::: "memory");
        }
        __syncthreads();

        uint32_t As_b = sb + (uint32_t)(c & 1) * STAGE_BYTES;
        uint32_t Ws_b = As_b + TILE_BYTES;

#pragma unroll
        for (int ks = 0; ks < 2; ks++) {
            const int kb = ks * 16;
            uint32_t b[4][2];
#pragma unroll
            for (int nt = 0; nt < 4; nt++) {
                uint32_t baddr = Ws_b + ((wn * 32 + nt * 8 + bl) * PADH + kb + bk8) * 2;
                ldsm_x2(b[nt][0], b[nt][1], baddr);
            }
#pragma unroll
            for (int mt = 0; mt < 4; mt++) {
                uint32_t a[4];
                uint32_t aaddr = As_b + ((wm * 64 + mt * 16 + lr) * PADH + kb + kc8) * 2;
                ldsm_x4(a, aaddr);
#pragma unroll
                for (int nt = 0; nt < 4; nt++)
                    mma_f16(acc[mt][nt], a, b[nt]);
            }
        }
        __syncthreads();
    }

    if constexpr (!HEAD) {
        __half* C = g_h1h;
#pragma unroll
        for (int mt = 0; mt < 4; mt++) {
#pragma unroll
            for (int nt = 0; nt < 4; nt++) {
                int col = n0 + wn * 32 + nt * 8 + 2 * t;
                float b0 = bias[col], b1 = bias[col + 1];
                int r0 = m0 + wm * 64 + mt * 16 + g;
                if (r0 < NN) {
                    __half2 h = __floats2half2_rn(fmaxf(acc[mt][nt][0] + b0, 0.f),
                                                  fmaxf(acc[mt][nt][1] + b1, 0.f));
                    *(uint32_t*)(C + (size_t)r0 * DH + col) = *(uint32_t*)&h;
                }
                int r1 = r0 + 8;
                if (r1 < NN) {
                    __half2 h = __floats2half2_rn(fmaxf(acc[mt][nt][2] + b0, 0.f),
                                                  fmaxf(acc[mt][nt][3] + b1, 0.f));
                    *(uint32_t*)(C + (size_t)r1 * DH + col) = *(uint32_t*)&h;
                }
            }
        }
    } else {
#pragma unroll
        for (int mt = 0; mt < 4; mt++) {
            float s0 = 0.f, s1 = 0.f;
#pragma unroll
            for (int nt = 0; nt < 4; nt++) {
                int col = n0 + wn * 32 + nt * 8 + 2 * t;
                float b0 = bias[col], b1 = bias[col + 1];
                float w0 = HW[col], w1 = HW[col + 1];
                s0 += fmaxf(acc[mt][nt][0] + b0, 0.f) * w0 +
                      fmaxf(acc[mt][nt][1] + b1, 0.f) * w1;
                s1 += fmaxf(acc[mt][nt][2] + b0, 0.f) * w0 +
                      fmaxf(acc[mt][nt][3] + b1, 0.f) * w1;
            }
            s0 += __shfl_xor_sync(0xffffffffu, s0, 1);
            s0 += __shfl_xor_sync(0xffffffffu, s0, 2);
            s1 += __shfl_xor_sync(0xffffffffu, s1, 1);
            s1 += __shfl_xor_sync(0xffffffffu, s1, 2);
            if (t == 0) {
                sred[wm * 64 + mt * 16 + g][wn]     = s0;
                sred[wm * 64 + mt * 16 + g + 8][wn] = s1;
            }
        }
        __syncthreads();
        if (tid < 128) {
            int r = m0 + tid;
            if (r < NN) {
                float v = (sred[tid][0] + sred[tid][1]) + (sred[tid][2] + sred[tid][3]);
                if (blockIdx.y == 0) v += HB[0];
                atomicAdd(&OUTP[r], v);   // 2 commutative contributions -> deterministic
            }
        }
    }
}

// ---------------- launch ----------------
extern "C" void kernel_launch(void* const* d_in, const int* in_sizes, int n_in,
                              void* d_out, int out_size) {
    const float* x   = (const float*)d_in[0];
    const int*   ei  = (const int*)d_in[1];
    const float* W1l = (const float*)d_in[2];
    const float* b1  = (const float*)d_in[3];
    const float* W1r = (const float*)d_in[4];
    const float* W2l = (const float*)d_in[5];
    const float* b2  = (const float*)d_in[6];
    const float* W2r = (const float*)d_in[7];
    const float* hw  = (const float*)d_in[8];
    const float* hb  = (const float*)d_in[9];
    float* out = (float*)d_out;

    int E = in_sizes[1] / 2;
    const int* srcp = ei;
    const int* dstp = ei + E;

    // fused conversion + degree count + scan-flag reset
    k_prep<<<(NN * 128 / 4 + 255) / 256, 256>>>(x, W1l, W1r, W2l, W2r, dstp, E);

    // single-pass CSR offsets (also zeroes d_out and g_deg) + fill
    k_scan<<<NBLK, SCAN_B>>>(E, out);
    k_fill<<<(E + 255) / 256, 256>>>(srcp, dstp, E);

    dim3 gemm_grid((NN + 127) / 128, 2);
    int  agg_blocks = (NN * 32 + 255) / 256;

    // Layer 1
    k_agg<128, 0><<<agg_blocks, 256>>>();
    k_gemm_h<128, 0><<<gemm_grid, 256>>>(b1, nullptr, nullptr, nullptr);

    // Layer 2 + head (fused)
    k_agg<256, 1><<<agg_blocks, 256>>>();
    k_gemm_h<256, 1><<<gemm_grid, 256>>>(b2, hw, hb, out);
}

// round 17
// speedup vs baseline: 1.0032x; 1.0032x over previous
#include <cuda_runtime.h>
#include <cuda_fp16.h>
#include <cstdint>

#define NN   50000
#define EMAX 800000
#define DH   256
#define SCAN_B 1024
#define NBLK ((NN + SCAN_B - 1) / SCAN_B)   // 49
#define PUB_FLAG 0x40000000

// ---------------- scratch (device globals; allocation-free) ----------------
__device__ __align__(16) int    g_deg[NN];        // zero at load; self-restored each launch
__device__ __align__(16) int    g_off[NN + 1];
__device__ __align__(16) int    g_cur[NN];
__device__ __align__(16) int    g_col[EMAX];
__device__ volatile int         g_pub[NBLK];      // packed aggregate | PUB_FLAG
__device__ __align__(16) __half g_xh  [(size_t)NN * 128];
__device__ __align__(16) __half g_w1lh[256 * 128];
__device__ __align__(16) __half g_w1rh[256 * 128];
__device__ __align__(16) __half g_w2lh[256 * 256];
__device__ __align__(16) __half g_w2rh[256 * 256];
__device__ __align__(16) __half g_m1h [(size_t)NN * 128];
__device__ __align__(16) __half g_h1h [(size_t)NN * 256];
__device__ __align__(16) __half g_m2h [(size_t)NN * 256];

// ---------------- helpers ----------------
__device__ __forceinline__ uint32_t smem_u32(const void* p) {
    uint32_t a;
    asm("{ .reg .u64 t; cvta.to.shared.u64 t, %1; cvt.u32.u64 %0, t; }" : "=r"(a) : "l"(p));
    return a;
}

__device__ __forceinline__ void cp16(uint32_t dst, const void* src, bool v) {
    int sz = v ? 16 : 0;
    asm volatile("cp.async.cg.shared.global [%0], [%1], 16, %2;\n"
                 :: "r"(dst), "l"(src), "r"(sz) : "memory");
}

__device__ __forceinline__ void mma_f16(float c[4], const uint32_t a[4], const uint32_t b[2]) {
    asm volatile(
        "mma.sync.aligned.m16n8k16.row.col.f32.f16.f16.f32 "
        "{%0,%1,%2,%3}, {%4,%5,%6,%7}, {%8,%9}, {%0,%1,%2,%3};\n"
        : "+f"(c[0]), "+f"(c[1]), "+f"(c[2]), "+f"(c[3])
        : "r"(a[0]), "r"(a[1]), "r"(a[2]), "r"(a[3]), "r"(b[0]), "r"(b[1]));
}

__device__ __forceinline__ void ldsm_x4(uint32_t r[4], uint32_t addr) {
    asm volatile("ldmatrix.sync.aligned.m8n8.x4.shared.b16 {%0,%1,%2,%3}, [%4];"
                 : "=r"(r[0]), "=r"(r[1]), "=r"(r[2]), "=r"(r[3]) : "r"(addr));
}

__device__ __forceinline__ void ldsm_x2(uint32_t& r0, uint32_t& r1, uint32_t addr) {
    asm volatile("ldmatrix.sync.aligned.m8n8.x2.shared.b16 {%0,%1}, [%2];"
                 : "=r"(r0), "=r"(r1) : "r"(addr));
}

__device__ __forceinline__ int warp_iscan(int x, int lane) {
#pragma unroll
    for (int o = 1; o < 32; o <<= 1) {
        int y = __shfl_up_sync(0xffffffffu, x, o);
        if (lane >= o) x += y;
    }
    return x;
}

// ---------------- fused prep: x->fp16, weights->fp16, degree count, flag reset ----
__global__ void k_prep(const float* __restrict__ x,
                       const float* __restrict__ W1l, const float* __restrict__ W1r,
                       const float* __restrict__ W2l, const float* __restrict__ W2r,
                       const int* __restrict__ dst, int E) {
    int i = blockIdx.x * blockDim.x + threadIdx.x;
    if (i < NBLK) g_pub[i] = 0;               // reset scan publication slots
    if (i < NN * 128 / 4) {
        float4 v = ((const float4*)x)[i];
        __half2 h0 = __floats2half2_rn(v.x, v.y);
        __half2 h1 = __floats2half2_rn(v.z, v.w);
        uint2 o;
        o.x = *(uint32_t*)&h0;
        o.y = *(uint32_t*)&h1;
        ((uint2*)g_xh)[i] = o;
    }
    if (i < 256 * 128) {
        g_w1lh[i] = __float2half_rn(W1l[i]);
        g_w1rh[i] = __float2half_rn(W1r[i]);
    }
    if (i < 256 * 256) {
        g_w2lh[i] = __float2half_rn(W2l[i]);
        g_w2rh[i] = __float2half_rn(W2r[i]);
    }
    if (i < E) atomicAdd(&g_deg[dst[i]], 1);  // g_deg pre-zeroed (load init / k_scan)
}

// ---------------- single-pass scan with decoupled lookback ----------------
__global__ void k_scan(int E, float* __restrict__ out) {
    __shared__ int wsum[32];
    __shared__ int s_prev;
    int t = threadIdx.x, lane = t & 31, w = t >> 5;
    int bid = blockIdx.x;
    int i = bid * SCAN_B + t;

    if (i < NN) out[i] = 0.f;                 // head accumulates into out later
    int v = 0;
    if (i < NN) {
        v = g_deg[i];
        g_deg[i] = 0;                         // self-restore for next launch
    }
    int x = warp_iscan(v, lane);
    if (lane == 31) wsum[w] = x;
    __syncthreads();
    if (w == 0) {
        int y = wsum[lane];
        int z = warp_iscan(y, lane);
        wsum[lane] = z - y;
    }
    __syncthreads();
    int incl = x + wsum[w];

    if (t == SCAN_B - 1) g_pub[bid] = incl | PUB_FLAG;

    if (w == 0) {
        int sum = 0;
        for (int b = bid - 1 - lane; b >= 0; b -= 32) {
            int p;
            do { p = g_pub[b]; } while (!(p & PUB_FLAG));
            sum += p & ~PUB_FLAG;
        }
#pragma unroll
        for (int o = 16; o; o >>= 1) sum += __shfl_xor_sync(0xffffffffu, sum, o);
        if (lane == 0) s_prev = sum;
    }
    __syncthreads();

    if (i < NN) {
        int e = incl - v + s_prev;
        g_off[i] = e;
        g_cur[i] = e;
    }
    if (i == 0) g_off[NN] = E;
}

__global__ void k_fill(const int* __restrict__ src, const int* __restrict__ dst, int E) {
    int e = blockIdx.x * blockDim.x + threadIdx.x;
    if (e < E) {
        int p = atomicAdd(&g_cur[dst[e]], 1);
        g_col[p] = src[e];
    }
}

// ---------------- aggregation: one warp per dst; pairwise half2 accumulate ----
// (reverted to the measured-best variant: regs 32, occ 81%, agg1 24.3us)
template <int D, int SEL>
__global__ void k_agg() {
    const __half* X   = (SEL == 0) ? g_xh  : g_h1h;
    __half*       OUT = (SEL == 0) ? g_m1h : g_m2h;

    int gw   = (blockIdx.x * blockDim.x + threadIdx.x) >> 5;
    int lane = threadIdx.x & 31;
    if (gw >= NN) return;

    constexpr int V2    = D / 128;             // uint2 (4 halves) per lane
    constexpr int BATCH = 8;                   // neighbors per inner step
    float acc[V2][4];
#pragma unroll
    for (int v = 0; v < V2; v++)
#pragma unroll
        for (int q = 0; q < 4; q++) acc[v][q] = 0.f;

    int s0 = g_off[gw], s1 = g_off[gw + 1];
    for (int i = s0; i < s1; i += 32) {
        int cnt = min(32, s1 - i);
        int my  = (lane < cnt) ? g_col[i + lane] : 0;
        int j = 0;
        for (; j + BATCH <= cnt; j += BATCH) {
            const uint2* p[BATCH];
#pragma unroll
            for (int b = 0; b < BATCH; b++) {
                int s = __shfl_sync(0xffffffffu, my, j + b);
                p[b] = (const uint2*)(X + (size_t)s * D);
            }
            uint2 u[BATCH][V2];
#pragma unroll
            for (int b = 0; b < BATCH; b++)
#pragma unroll
                for (int v = 0; v < V2; v++) u[b][v] = p[b][v * 32 + lane];
            // pairwise half2 add (1 rounding at element magnitude), then fp32 accum
#pragma unroll
            for (int b = 0; b < BATCH; b += 2)
#pragma unroll
                for (int v = 0; v < V2; v++) {
                    __half2 px = __hadd2(*(__half2*)&u[b][v].x, *(__half2*)&u[b + 1][v].x);
                    __half2 py = __hadd2(*(__half2*)&u[b][v].y, *(__half2*)&u[b + 1][v].y);
                    float2 f0 = __half22float2(px);
                    float2 f1 = __half22float2(py);
                    acc[v][0] += f0.x; acc[v][1] += f0.y;
                    acc[v][2] += f1.x; acc[v][3] += f1.y;
                }
        }
        for (; j < cnt; j++) {                 // tail: exact fp32 path
            int s = __shfl_sync(0xffffffffu, my, j);
            const uint2* p = (const uint2*)(X + (size_t)s * D);
#pragma unroll
            for (int v = 0; v < V2; v++) {
                uint2 u = p[v * 32 + lane];
                float2 f0 = __half22float2(*(__half2*)&u.x);
                float2 f1 = __half22float2(*(__half2*)&u.y);
                acc[v][0] += f0.x; acc[v][1] += f0.y;
                acc[v][2] += f1.x; acc[v][3] += f1.y;
            }
        }
    }
    int deg = s1 - s0;
    float inv = 1.0f / (float)max(deg, 1);
    uint2* orow = (uint2*)(OUT + (size_t)gw * D);
#pragma unroll
    for (int v = 0; v < V2; v++) {
        __half2 h0 = __floats2half2_rn(acc[v][0] * inv, acc[v][1] * inv);
        __half2 h1 = __floats2half2_rn(acc[v][2] * inv, acc[v][3] * inv);
        uint2 o;
        o.x = *(uint32_t*)&h0;
        o.y = *(uint32_t*)&h1;
        orow[v * 32 + lane] = o;
    }
}

// ---------------- fp16 mma.sync fused two-input GEMM + bias + ReLU ---------------
// SEL==0: C=h1 (fp16 store). SEL==1: head fused — out[n] += relu(row)·head_w (+hb).
// Single-sync pipeline: wait(c) -> sync -> issue(c+1) -> compute(c).
// Sync(c) proves all warps finished compute(c-1), so writing stage (c+1)&1
// cannot race readers of that stage; load c+1 still overlaps compute(c).
#define PADH 40                              // halves per smem row (80 B)
#define TILE_BYTES (128 * PADH * 2)          // 10240
#define STAGE_BYTES (2 * TILE_BYTES)         // 20480 (A + W)
#define STAGE_HALVES (STAGE_BYTES / 2)

template <int K, int SEL>
__device__ __forceinline__ void load_chunk(int c, int m0, int n0, uint32_t sb, int tid) {
    constexpr int NCH = (2 * K) / 32;
    const __half* A1 = (SEL == 0) ? g_m1h  : g_m2h;
    const __half* A2 = (SEL == 0) ? g_xh   : g_h1h;
    const __half* W1 = (SEL == 0) ? g_w1lh : g_w2lh;
    const __half* W2 = (SEL == 0) ? g_w1rh : g_w2rh;

    int st = c & 1;
    int ss = (c >= NCH / 2);
    int k0 = (c - ss * (NCH / 2)) * 32;
    const __half* A = ss ? A2 : A1;
    const __half* W = ss ? W2 : W1;

    int row = tid >> 1;          // 0..127
    int q   = (tid & 1) * 2;     // 16B-chunk 0 or 2

    uint32_t base = sb + (uint32_t)st * STAGE_BYTES;
    uint32_t adst = base + row * (PADH * 2) + q * 16;
    uint32_t wdst = adst + TILE_BYTES;

    int  arow = m0 + row;
    bool v    = (arow < NN);
    int  ar   = v ? arow : 0;
    const __half* asrc = A + (size_t)ar * K + k0 + q * 8;
    const __half* wsrc = W + (size_t)(n0 + row) * K + k0 + q * 8;
    cp16(adst,      asrc,     v);
    cp16(adst + 16, asrc + 8, v);
    cp16(wdst,      wsrc,     true);
    cp16(wdst + 16, wsrc + 8, true);
    asm volatile("cp.async.commit_group;" ::: "memory");
}

template <int K, int SEL>
__global__ void __launch_bounds__(256, 2) k_gemm_h(const float* __restrict__ bias,
                                                   const float* __restrict__ HW,
                                                   const float* __restrict__ HB,
                                                   float* __restrict__ OUTP) {
    constexpr bool HEAD = (SEL == 1);
    constexpr int  NCH  = (2 * K) / 32;

    __shared__ __align__(16) __half smem[2 * STAGE_HALVES];
    __shared__ float sred[128][4];
    uint32_t sb = smem_u32(smem);

    const int tid  = threadIdx.x;
    const int warp = tid >> 5;
    const int lane = tid & 31;
    const int g    = lane >> 2;
    const int t    = lane & 3;
    const int m0   = blockIdx.x * 128;
    const int n0   = blockIdx.y * 128;
    const int wm   = warp >> 2;   // 0..1
    const int wn   = warp & 3;    // 0..3

    const int lr  = lane & 15;
    const int kc8 = (lane >> 4) * 8;
    const int bl  = lane & 7;
    const int bk8 = ((lane >> 3) & 1) * 8;

    float acc[4][4][4];
#pragma unroll
    for (int i = 0; i < 4; i++)
#pragma unroll
        for (int j = 0; j < 4; j++)
#pragma unroll
            for (int c = 0; c < 4; c++) acc[i][j][c] = 0.f;

    load_chunk<K, SEL>(0, m0, n0, sb, tid);

    for (int c = 0; c < NCH; c++) {
        asm volatile("cp.async.wait_group 0;" ::: "memory");   // chunk c resident
        __syncthreads();                                       // all warps done with stage (c+1)&1
        if (c + 1 < NCH) load_chunk<K, SEL>(c + 1, m0, n0, sb, tid);

        uint32_t As_b = sb + (uint32_t)(c & 1) * STAGE_BYTES;
        uint32_t Ws_b = As_b + TILE_BYTES;

#pragma unroll
        for (int ks = 0; ks < 2; ks++) {
            const int kb = ks * 16;
            uint32_t b[4][2];
#pragma unroll
            for (int nt = 0; nt < 4; nt++) {
                uint32_t baddr = Ws_b + ((wn * 32 + nt * 8 + bl) * PADH + kb + bk8) * 2;
                ldsm_x2(b[nt][0], b[nt][1], baddr);
            }
#pragma unroll
            for (int mt = 0; mt < 4; mt++) {
                uint32_t a[4];
                uint32_t aaddr = As_b + ((wm * 64 + mt * 16 + lr) * PADH + kb + kc8) * 2;
                ldsm_x4(a, aaddr);
#pragma unroll
                for (int nt = 0; nt < 4; nt++)
                    mma_f16(acc[mt][nt], a, b[nt]);
            }
        }
    }

    if constexpr (!HEAD) {
        __half* C = g_h1h;
#pragma unroll
        for (int mt = 0; mt < 4; mt++) {
#pragma unroll
            for (int nt = 0; nt < 4; nt++) {
                int col = n0 + wn * 32 + nt * 8 + 2 * t;
                float b0 = bias[col], b1 = bias[col + 1];
                int r0 = m0 + wm * 64 + mt * 16 + g;
                if (r0 < NN) {
                    __half2 h = __floats2half2_rn(fmaxf(acc[mt][nt][0] + b0, 0.f),
                                                  fmaxf(acc[mt][nt][1] + b1, 0.f));
                    *(uint32_t*)(C + (size_t)r0 * DH + col) = *(uint32_t*)&h;
                }
                int r1 = r0 + 8;
                if (r1 < NN) {
                    __half2 h = __floats2half2_rn(fmaxf(acc[mt][nt][2] + b0, 0.f),
                                                  fmaxf(acc[mt][nt][3] + b1, 0.f));
                    *(uint32_t*)(C + (size_t)r1 * DH + col) = *(uint32_t*)&h;
                }
            }
        }
    } else {
#pragma unroll
        for (int mt = 0; mt < 4; mt++) {
            float s0 = 0.f, s1 = 0.f;
#pragma unroll
            for (int nt = 0; nt < 4; nt++) {
                int col = n0 + wn * 32 + nt * 8 + 2 * t;
                float b0 = bias[col], b1 = bias[col + 1];
                float w0 = HW[col], w1 = HW[col + 1];
                s0 += fmaxf(acc[mt][nt][0] + b0, 0.f) * w0 +
                      fmaxf(acc[mt][nt][1] + b1, 0.f) * w1;
                s1 += fmaxf(acc[mt][nt][2] + b0, 0.f) * w0 +
                      fmaxf(acc[mt][nt][3] + b1, 0.f) * w1;
            }
            s0 += __shfl_xor_sync(0xffffffffu, s0, 1);
            s0 += __shfl_xor_sync(0xffffffffu, s0, 2);
            s1 += __shfl_xor_sync(0xffffffffu, s1, 1);
            s1 += __shfl_xor_sync(0xffffffffu, s1, 2);
            if (t == 0) {
                sred[wm * 64 + mt * 16 + g][wn]     = s0;
                sred[wm * 64 + mt * 16 + g + 8][wn] = s1;
            }
        }
        __syncthreads();
        if (tid < 128) {
            int r = m0 + tid;
            if (r < NN) {
                float v = (sred[tid][0] + sred[tid][1]) + (sred[tid][2] + sred[tid][3]);
                if (blockIdx.y == 0) v += HB[0];
                atomicAdd(&OUTP[r], v);   // 2 commutative contributions -> deterministic
            }
        }
    }
}

// ---------------- launch ----------------
extern "C" void kernel_launch(void* const* d_in, const int* in_sizes, int n_in,
                              void* d_out, int out_size) {
    const float* x   = (const float*)d_in[0];
    const int*   ei  = (const int*)d_in[1];
    const float* W1l = (const float*)d_in[2];
    const float* b1  = (const float*)d_in[3];
    const float* W1r = (const float*)d_in[4];
    const float* W2l = (const float*)d_in[5];
    const float* b2  = (const float*)d_in[6];
    const float* W2r = (const float*)d_in[7];
    const float* hw  = (const float*)d_in[8];
    const float* hb  = (const float*)d_in[9];
    float* out = (float*)d_out;

    int E = in_sizes[1] / 2;
    const int* srcp = ei;
    const int* dstp = ei + E;

    // fused conversion + degree count + scan-flag reset
    k_prep<<<(NN * 128 / 4 + 255) / 256, 256>>>(x, W1l, W1r, W2l, W2r, dstp, E);

    // single-pass CSR offsets (also zeroes d_out and g_deg) + fill
    k_scan<<<NBLK, SCAN_B>>>(E, out);
    k_fill<<<(E + 255) / 256, 256>>>(srcp, dstp, E);

    dim3 gemm_grid((NN + 127) / 128, 2);
    int  agg_blocks = (NN * 32 + 255) / 256;

    // Layer 1
    k_agg<128, 0><<<agg_blocks, 256>>>();
    k_gemm_h<128, 0><<<gemm_grid, 256>>>(b1, nullptr, nullptr, nullptr);

    // Layer 2 + head (fused)
    k_agg<256, 1><<<agg_blocks, 256>>>();
    k_gemm_h<256, 1><<<gemm_grid, 256>>>(b2, hw, hb, out);
}